// round 16
// baseline (speedup 1.0000x reference)
#include <cuda_runtime.h>
#include <cuda_bf16.h>
#include <math.h>
#include <stdint.h>

// GptOssTopKRouter via legacy mma.sync (bf16x3 split emulating fp32 GEMM).
// 4-way K-split accumulator sets to cut the per-accumulator HMMA RAW chain
// from 540 links to <=180. BM=64, 256 threads, KC=32, pre-converted weights.
// logits = hidden[T,H] @ weight[E,H]^T + bias ; top-4 ; softmax over the 4.
// Output f32: scores [T,4] at 0, indices-as-float at out_size/2.
// Near-tie rows (adjacent top-5 gap < GAP_THRESH) re-ranked with fp64 dots.

#define TOPK 4
#define NCAND 6
#define GAP_THRESH 1e-3f

#define BM 64
#define BN 128
#define KC 32                 // k elements per chunk
#define LGS 132               // padded logits stride (floats)
#define MAXCH 128             // max K chunks supported (H/KC = 90 here)

// smem layout (bytes)
#define SM_BIAS     0                         // 512 B
#define SM_TILES    1024
#define OFF_AHI     0
#define OFF_ALO     4096
#define OFF_BHI     8192
#define OFF_BLO     16384
#define STAGE_BYTES 24576                     // Ahi,Alo,Bhi,Blo
#define SM_LOGITS   1024                      // aliases stages (after GEMM)
#define SMEM_TOTAL  (1024 + 2*STAGE_BYTES)    // 50176 (logits 64*132*4=33792 fits)

// pre-converted weight tiles: [chunk][8192 bytes], pre-swizzled
__device__ __align__(16) char g_wt_hi[MAXCH * 8192];
__device__ __align__(16) char g_wt_lo[MAXCH * 8192];

// swizzled byte offset within a tile: 64B rows, 16B units c16 in 0..3
__device__ __forceinline__ uint32_t swz(int row, int c16) {
    return (uint32_t)(row * 64 + ((c16 ^ ((row >> 1) & 3)) << 4));
}

__device__ __forceinline__ uint32_t smem_u32(const void* p){
    uint32_t a;
    asm("{ .reg .u64 t; cvta.to.shared.u64 t, %1; cvt.u32.u64 %0, t; }":"=r"(a):"l"(p));
    return a;
}

__device__ __forceinline__ void ldsm4(uint32_t r[4], uint32_t addr){
    asm volatile("ldmatrix.sync.aligned.m8n8.x4.shared.b16 {%0,%1,%2,%3}, [%4];"
        : "=r"(r[0]),"=r"(r[1]),"=r"(r[2]),"=r"(r[3]) : "r"(addr));
}

__device__ __forceinline__ void mma_bf16(float d[4], const uint32_t a[4], const uint32_t b[2]){
    asm volatile("mma.sync.aligned.m16n8k16.row.col.f32.bf16.bf16.f32 "
        "{%0,%1,%2,%3}, {%4,%5,%6,%7}, {%8,%9}, {%0,%1,%2,%3};"
        : "+f"(d[0]),"+f"(d[1]),"+f"(d[2]),"+f"(d[3])
        : "r"(a[0]),"r"(a[1]),"r"(a[2]),"r"(a[3]), "r"(b[0]),"r"(b[1]));
}

__device__ __forceinline__ void cpa16(uint32_t d, const void* s){
    asm volatile("cp.async.cg.shared.global [%0], [%1], 16;" :: "r"(d), "l"(s));
}

// split 8 fp32 into packed bf16x2 hi[4] / lo[4] (low half = even element)
__device__ __forceinline__ void split8(float4 f0, float4 f1, uint32_t hi[4], uint32_t lo[4]){
    float f[8] = {f0.x,f0.y,f0.z,f0.w,f1.x,f1.y,f1.z,f1.w};
#pragma unroll
    for (int i = 0; i < 4; i++) {
        uint32_t hp;
        asm("cvt.rn.bf16x2.f32 %0, %1, %2;" : "=r"(hp) : "f"(f[2*i+1]), "f"(f[2*i]));
        float h0 = __uint_as_float(hp << 16);
        float h1 = __uint_as_float(hp & 0xFFFF0000u);
        float l0 = f[2*i]   - h0;
        float l1 = f[2*i+1] - h1;
        uint32_t lp;
        asm("cvt.rn.bf16x2.f32 %0, %1, %2;" : "=r"(lp) : "f"(l1), "f"(l0));
        hi[i] = hp; lo[i] = lp;
    }
}

// ---- pre-pass: convert weight[128 x H] fp32 -> pre-swizzled bf16 hi/lo tiles ----
__global__ void convert_weight_kernel(const float* __restrict__ weight, int H)
{
    const int t  = blockIdx.x;         // chunk
    const int kb = t * KC;
#pragma unroll 1
    for (int u = threadIdx.x; u < 512; u += 256) {   // 128 rows x 4 segs
        int row = u >> 2, lq = u & 3;
        const float* bp = &weight[(size_t)row * H + kb + lq * 8];
        float4 f0 = *reinterpret_cast<const float4*>(bp);
        float4 f1 = *reinterpret_cast<const float4*>(bp + 4);
        uint32_t hi[4], lo[4];
        split8(f0, f1, hi, lo);
        uint32_t off = (uint32_t)t * 8192u + swz(row, lq);
        *reinterpret_cast<uint4*>(g_wt_hi + off) = make_uint4(hi[0],hi[1],hi[2],hi[3]);
        *reinterpret_cast<uint4*>(g_wt_lo + off) = make_uint4(lo[0],lo[1],lo[2],lo[3]);
    }
}

__global__ __launch_bounds__(256, 1)
void router_mma_kernel(const float* __restrict__ hidden,
                       const float* __restrict__ weight,
                       const float* __restrict__ bias,
                       float* __restrict__ out,
                       int T, int H, int E, int idx_base)
{
    extern __shared__ char smem[];
    float* bias_s = (float*)(smem + SM_BIAS);
    float* logits = (float*)(smem + SM_LOGITS);
    const uint32_t sbase = smem_u32(smem);

    const int tid  = threadIdx.x;
    const int wid  = tid >> 5;
    const int lane = tid & 31;
    const int row0 = blockIdx.x * BM;

    if (tid < BN) bias_s[tid] = bias[tid];

    // A loader mapping: 64 rows x 4 segs = 256 -> 1 seg/thread
    const int lrow = tid >> 2;       // 0..63
    const int lq   = tid & 3;        // 8-float segment

    // warp tile: 2 (M) x 4 (N) warps, each 32x32
    const int wm = (wid & 1) * 32;
    const int wn = (wid >> 1) * 32;

    // 4 independent accumulator sets per (mt,nt) tile -> short RAW chains
    float d[4][2][4][4];
#pragma unroll
    for (int s = 0; s < 4; s++)
#pragma unroll
        for (int mt = 0; mt < 2; mt++)
#pragma unroll
            for (int nt = 0; nt < 4; nt++)
#pragma unroll
                for (int k = 0; k < 4; k++) d[s][mt][nt][k] = 0.0f;

    float4 stg0, stg1;
    const int nch = H / KC;    // 90

    // ---- prologue: cp.async B chunk0 into stage0 ; LDG A chunk0 ----
    {
        uint32_t dH = sbase + SM_TILES + OFF_BHI + tid * 32;
        uint32_t dL = sbase + SM_TILES + OFF_BLO + tid * 32;
        const char* sH = g_wt_hi + tid * 32;
        const char* sL = g_wt_lo + tid * 32;
        cpa16(dH, sH); cpa16(dH + 16, sH + 16);
        cpa16(dL, sL); cpa16(dL + 16, sL + 16);
        asm volatile("cp.async.commit_group;" ::: "memory");

        const float* ap = &hidden[(size_t)(row0 + lrow) * H + lq * 8];
        stg0 = *reinterpret_cast<const float4*>(ap);
        stg1 = *reinterpret_cast<const float4*>(ap + 4);
    }

    for (int t = 0; t < nch; t++) {
        char* stage_p = smem + SM_TILES + (t & 1) * STAGE_BYTES;
        const uint32_t stage_a = sbase + SM_TILES + (t & 1) * STAGE_BYTES;

        // ---- 1. convert A(t) + STS ----
        {
            uint32_t hi[4], lo[4];
            uint32_t offA = swz(lrow, lq);
            split8(stg0, stg1, hi, lo);
            *reinterpret_cast<uint4*>(stage_p + OFF_AHI + offA) = make_uint4(hi[0],hi[1],hi[2],hi[3]);
            *reinterpret_cast<uint4*>(stage_p + OFF_ALO + offA) = make_uint4(lo[0],lo[1],lo[2],lo[3]);
        }

        // ---- 2. LDG A(t+1) ----
        if (t + 1 < nch) {
            int kb = (t + 1) * KC;
            const float* ap = &hidden[(size_t)(row0 + lrow) * H + kb + lq * 8];
            stg0 = *reinterpret_cast<const float4*>(ap);
            stg1 = *reinterpret_cast<const float4*>(ap + 4);
        }

        // ---- 3. B(t) arrived ; publish ----
        asm volatile("cp.async.wait_group 0;" ::: "memory");
        __syncthreads();

        // ---- 4. cp.async B(t+1) into other stage (overlaps MMA) ----
        if (t + 1 < nch) {
            uint32_t st1 = sbase + SM_TILES + ((t + 1) & 1) * STAGE_BYTES;
            uint32_t dH = st1 + OFF_BHI + tid * 32;
            uint32_t dL = st1 + OFF_BLO + tid * 32;
            const char* sH = g_wt_hi + (size_t)(t + 1) * 8192 + tid * 32;
            const char* sL = g_wt_lo + (size_t)(t + 1) * 8192 + tid * 32;
            cpa16(dH, sH); cpa16(dH + 16, sH + 16);
            cpa16(dL, sL); cpa16(dL + 16, sL + 16);
            asm volatile("cp.async.commit_group;" ::: "memory");
        }

        // ---- 5. MMA phase: 2 k16 steps; terms scattered over 4 acc sets ----
#pragma unroll
        for (int s2 = 0; s2 < 2; s2++) {
            uint32_t Ah[2][4], Al[2][4], Bh[2][4], Bl[2][4];
#pragma unroll
            for (int mt = 0; mt < 2; mt++) {
                int r = wm + mt * 16 + (lane & 15);
                int c16 = 2 * s2 + (lane >> 4);
                uint32_t ao = swz(r, c16);
                ldsm4(Ah[mt], stage_a + OFF_AHI + ao);
                ldsm4(Al[mt], stage_a + OFF_ALO + ao);
            }
#pragma unroll
            for (int p = 0; p < 2; p++) {
                int nr = wn + p * 16 + (lane & 7) + ((lane >> 4) & 1) * 8;
                int c16 = 2 * s2 + ((lane >> 3) & 1);
                uint32_t bo = swz(nr, c16);
                ldsm4(Bh[p], stage_a + OFF_BHI + bo);
                ldsm4(Bl[p], stage_a + OFF_BLO + bo);
            }
            // hi*hi  -> set (2*s2+0)&3
#pragma unroll
            for (int mt = 0; mt < 2; mt++)
#pragma unroll
                for (int nt = 0; nt < 4; nt++)
                    mma_bf16(d[(2*s2+0)&3][mt][nt], Ah[mt], &Bh[nt >> 1][(nt & 1) * 2]);
            // hi*lo  -> set (2*s2+1)&3
#pragma unroll
            for (int mt = 0; mt < 2; mt++)
#pragma unroll
                for (int nt = 0; nt < 4; nt++)
                    mma_bf16(d[(2*s2+1)&3][mt][nt], Ah[mt], &Bl[nt >> 1][(nt & 1) * 2]);
            // lo*hi  -> set (2*s2+2)&3
#pragma unroll
            for (int mt = 0; mt < 2; mt++)
#pragma unroll
                for (int nt = 0; nt < 4; nt++)
                    mma_bf16(d[(2*s2+2)&3][mt][nt], Al[mt], &Bh[nt >> 1][(nt & 1) * 2]);
        }
    }

    __syncthreads();   // all ldmatrix done before logits alias the stage buffers

    // ---- reduce sets, add bias -> smem logits[64][LGS] ----
#pragma unroll
    for (int mt = 0; mt < 2; mt++)
#pragma unroll
        for (int nt = 0; nt < 4; nt++) {
            float v0 = (d[0][mt][nt][0] + d[1][mt][nt][0]) + (d[2][mt][nt][0] + d[3][mt][nt][0]);
            float v1 = (d[0][mt][nt][1] + d[1][mt][nt][1]) + (d[2][mt][nt][1] + d[3][mt][nt][1]);
            float v2 = (d[0][mt][nt][2] + d[1][mt][nt][2]) + (d[2][mt][nt][2] + d[3][mt][nt][2]);
            float v3 = (d[0][mt][nt][3] + d[1][mt][nt][3]) + (d[2][mt][nt][3] + d[3][mt][nt][3]);
            int m = wm + mt * 16 + (lane >> 2);
            int n = wn + nt * 8 + 2 * (lane & 3);
            logits[m * LGS + n]           = v0 + bias_s[n];
            logits[m * LGS + n + 1]       = v1 + bias_s[n + 1];
            logits[(m + 8) * LGS + n]     = v2 + bias_s[n];
            logits[(m + 8) * LGS + n + 1] = v3 + bias_s[n + 1];
        }
    __syncthreads();

    // ---- per-row top-6 + softmax; warp w handles rows 8w..8w+7 ----
#pragma unroll 1
    for (int rr = 0; rr < 8; rr++) {
        const int r = wid * 8 + rr;
        const int row = row0 + r;
        float v[4];
        bool taken[4] = {false, false, false, false};
#pragma unroll
        for (int j = 0; j < 4; j++) v[j] = logits[r * LGS + lane + 32 * j];

        float topv[NCAND];
        int   topi[NCAND];
#pragma unroll 1
        for (int k = 0; k < NCAND; k++) {
            float bv = -INFINITY;
            int   bi = 0x7FFFFFFF;
#pragma unroll
            for (int j = 0; j < 4; j++)
                if (!taken[j] && v[j] > bv) { bv = v[j]; bi = lane + 32 * j; }
#pragma unroll
            for (int off = 16; off > 0; off >>= 1) {
                float ov = __shfl_xor_sync(0xFFFFFFFFu, bv, off);
                int   oi = __shfl_xor_sync(0xFFFFFFFFu, bi, off);
                if (ov > bv || (ov == bv && oi < bi)) { bv = ov; bi = oi; }
            }
            topv[k] = bv;
            topi[k] = bi;
            if ((bi & 31) == lane) taken[bi >> 5] = true;
        }

        bool need = (topv[0]-topv[1] < GAP_THRESH) || (topv[1]-topv[2] < GAP_THRESH) ||
                    (topv[2]-topv[3] < GAP_THRESH) || (topv[3]-topv[4] < GAP_THRESH);

        if (!need) {
            if (lane == 0) {
                float mx = topv[0];
                float e0 = expf(topv[0]-mx), e1 = expf(topv[1]-mx);
                float e2 = expf(topv[2]-mx), e3 = expf(topv[3]-mx);
                float inv = 1.0f / (e0+e1+e2+e3);
                float* so = out + (size_t)row * TOPK;
                so[0]=e0*inv; so[1]=e1*inv; so[2]=e2*inv; so[3]=e3*inv;
                float* io = out + idx_base + (size_t)row * TOPK;
                io[0]=(float)topi[0]; io[1]=(float)topi[1];
                io[2]=(float)topi[2]; io[3]=(float)topi[3];
            }
        } else {
            // fp64 refinement of the 6 candidates (whole warp participates)
            const float* hrow = hidden + (size_t)row * H;
            double rv[NCAND];
#pragma unroll 1
            for (int c = 0; c < NCAND; c++) {
                const float* wrow = weight + (size_t)topi[c] * H;
                double s0 = 0.0, s1 = 0.0;
                for (int j = lane; j < H; j += 64) {
                    s0 = fma((double)hrow[j],      (double)wrow[j],      s0);
                    s1 = fma((double)hrow[j + 32], (double)wrow[j + 32], s1);
                }
                double acc = s0 + s1;
#pragma unroll
                for (int off = 16; off > 0; off >>= 1)
                    acc += __shfl_xor_sync(0xFFFFFFFFu, acc, off);
                rv[c] = acc + (double)bias[topi[c]];
            }
            if (lane == 0) {
                int ri[NCAND];
#pragma unroll
                for (int c = 0; c < NCAND; c++) ri[c] = topi[c];
#pragma unroll
                for (int a = 0; a < TOPK; a++) {
                    int best = a;
#pragma unroll
                    for (int b = a + 1; b < NCAND; b++)
                        if (rv[b] > rv[best] || (rv[b] == rv[best] && ri[b] < ri[best])) best = b;
                    double tvv = rv[a]; rv[a] = rv[best]; rv[best] = tvv;
                    int    tii = ri[a]; ri[a] = ri[best]; ri[best] = tii;
                }
                double mx = rv[0];
                float e0 = expf((float)(rv[0]-mx)), e1 = expf((float)(rv[1]-mx));
                float e2 = expf((float)(rv[2]-mx)), e3 = expf((float)(rv[3]-mx));
                float inv = 1.0f / (e0+e1+e2+e3);
                float* so = out + (size_t)row * TOPK;
                so[0]=e0*inv; so[1]=e1*inv; so[2]=e2*inv; so[3]=e3*inv;
                float* io = out + idx_base + (size_t)row * TOPK;
                io[0]=(float)ri[0]; io[1]=(float)ri[1]; io[2]=(float)ri[2]; io[3]=(float)ri[3];
            }
        }
    }
}

extern "C" void kernel_launch(void* const* d_in, const int* in_sizes, int n_in,
                              void* d_out, int out_size)
{
    const float* hidden = (const float*)d_in[0];
    const float* weight = (const float*)d_in[1];
    const float* bias   = (const float*)d_in[2];
    float* out = (float*)d_out;

    const int E = in_sizes[2];                 // 128
    const int H = in_sizes[1] / E;             // 2880
    const int T = in_sizes[0] / H;             // 16384
    const int idx_base = out_size / 2;
    const int nch = H / KC;                    // 90

    convert_weight_kernel<<<nch, 256>>>(weight, H);

    cudaFuncSetAttribute(router_mma_kernel,
                         cudaFuncAttributeMaxDynamicSharedMemorySize, SMEM_TOTAL);
    dim3 grid(T / BM);     // 256
    dim3 block(256);
    router_mma_kernel<<<grid, block, SMEM_TOTAL>>>(hidden, weight, bias, out, T, H, E, idx_base);
}